// round 2
// baseline (speedup 1.0000x reference)
#include <cuda_runtime.h>

// ---------------------------------------------------------------------------
// SSMBlock (Mamba-style) on GB300 — Round 1: fp32-correct baseline.
//   B=2, L=2048, D_MODEL=1024, D_INNER=2048, D_STATE=16, D_CONV=4
// Pipeline:
//   1. gemm_k<false>: xz = x @ W_in + b_in            (4096 x 4096, K=1024)
//   2. conv_silu   : xi = silu(causal depthwise conv)  -> g_xs
//   3. aprep       : A = -exp(clip(A_log,-10,2))
//   4. bc_kernel   : [B|C] = xi @ [W_B|W_C] + bias     -> g_bc (4096 x 32)
//   5. scan_kernel : sequential selective scan          -> g_ys
//   6. gemm_k<true>: out = (ys * sigmoid(z)) @ W_out + b_out
// ---------------------------------------------------------------------------

#define TOK   4096      // B * L tokens
#define DM    1024
#define DI    2048
#define DS    16
#define LSEQ  2048
#define NB    2

__device__ float g_xz[(size_t)TOK * 2 * DI];   // 64 MB
__device__ float g_xs[(size_t)TOK * DI];       // 32 MB
__device__ float g_bc[(size_t)TOK * 32];       // 512 KB  (B[0:16), C[16:32))
__device__ float g_ys[(size_t)TOK * DI];       // 32 MB
__device__ float g_A [DI * DS];

__device__ __forceinline__ float sigmoidf_(float v) {
    return 1.0f / (1.0f + __expf(-v));
}

// ---------------------------------------------------------------------------
// Tiled fp32 GEMM, 128x128 tiles, BK=8, 256 threads, 8x8 per-thread microtile.
// GATE=false: C(=g_xz) = Ap[M,K] @ Bp[K,N] + bias
// GATE=true : Cp       = (g_ys * sigmoid(z from g_xz)) @ Bp + bias
// ---------------------------------------------------------------------------
template<int M, int N, int K, bool GATE>
__global__ __launch_bounds__(256)
void gemm_k(const float* __restrict__ Ap, const float* __restrict__ Bp,
            const float* __restrict__ bias, float* __restrict__ Cp)
{
    __shared__ float As[8][128];
    __shared__ float Bs[8][128];

    const int tid  = threadIdx.x;
    const int tx   = tid & 15;          // 0..15 -> 8 cols each
    const int ty   = tid >> 4;          // 0..15 -> 8 rows each
    const int row0 = blockIdx.y * 128;
    const int col0 = blockIdx.x * 128;

    const int aRow = tid >> 1;          // 0..127
    const int aK   = (tid & 1) * 4;     // 0 or 4
    const int bK   = tid >> 5;          // 0..7
    const int bCol = (tid & 31) * 4;    // 0..124

    float acc[8][8];
#pragma unroll
    for (int i = 0; i < 8; i++)
#pragma unroll
        for (int j = 0; j < 8; j++) acc[i][j] = 0.0f;

    for (int k0 = 0; k0 < K; k0 += 8) {
        float4 av, bv;
        if (!GATE) {
            av = *(const float4*)(Ap + (size_t)(row0 + aRow) * K + k0 + aK);
        } else {
            const size_t r = (size_t)(row0 + aRow);
            const float4 yv = *(const float4*)(g_ys + r * DI + k0 + aK);
            const float4 zv = *(const float4*)(g_xz + r * (2 * DI) + DI + k0 + aK);
            av.x = yv.x * sigmoidf_(zv.x);
            av.y = yv.y * sigmoidf_(zv.y);
            av.z = yv.z * sigmoidf_(zv.z);
            av.w = yv.w * sigmoidf_(zv.w);
        }
        bv = *(const float4*)(Bp + (size_t)(k0 + bK) * N + col0 + bCol);

        __syncthreads();   // previous tile fully consumed
        As[aK + 0][aRow] = av.x;
        As[aK + 1][aRow] = av.y;
        As[aK + 2][aRow] = av.z;
        As[aK + 3][aRow] = av.w;
        *(float4*)(&Bs[bK][bCol]) = bv;
        __syncthreads();

#pragma unroll
        for (int kk = 0; kk < 8; kk++) {
            float a[8], b[8];
            *(float4*)(a)     = *(const float4*)(&As[kk][ty * 8]);
            *(float4*)(a + 4) = *(const float4*)(&As[kk][ty * 8 + 4]);
            *(float4*)(b)     = *(const float4*)(&Bs[kk][tx * 8]);
            *(float4*)(b + 4) = *(const float4*)(&Bs[kk][tx * 8 + 4]);
#pragma unroll
            for (int i = 0; i < 8; i++)
#pragma unroll
                for (int j = 0; j < 8; j++)
                    acc[i][j] = fmaf(a[i], b[j], acc[i][j]);
        }
    }

    float* Cout = GATE ? Cp : g_xz;
#pragma unroll
    for (int i = 0; i < 8; i++) {
        const size_t row = (size_t)(row0 + ty * 8 + i);
#pragma unroll
        for (int j = 0; j < 8; j += 4) {
            const int col = col0 + tx * 8 + j;
            float4 o;
            o.x = acc[i][j + 0] + bias[col + 0];
            o.y = acc[i][j + 1] + bias[col + 1];
            o.z = acc[i][j + 2] + bias[col + 2];
            o.w = acc[i][j + 3] + bias[col + 3];
            *(float4*)(Cout + row * N + col) = o;
        }
    }
}

// ---------------------------------------------------------------------------
// Depthwise causal conv (d_conv=4) + bias + SiLU. One thread per channel d,
// rolling 4-register window over a 64-step L chunk. Reads each input once.
// grid (16, 32, 2), block 128.
// ---------------------------------------------------------------------------
__global__ __launch_bounds__(128)
void conv_silu(const float* __restrict__ Wc, const float* __restrict__ bc)
{
    const int d  = blockIdx.x * 128 + threadIdx.x;   // 0..2047
    const int b  = blockIdx.z;
    const int l0 = blockIdx.y * 64;

    const float w0 = Wc[d * 4 + 0], w1 = Wc[d * 4 + 1];
    const float w2 = Wc[d * 4 + 2], w3 = Wc[d * 4 + 3];
    const float bias = bc[d];

    const float* xi = g_xz + (size_t)(b * LSEQ) * (2 * DI) + d;   // stride 2*DI over l
    float x0 = (l0 - 3 >= 0) ? xi[(size_t)(l0 - 3) * (2 * DI)] : 0.0f;
    float x1 = (l0 - 2 >= 0) ? xi[(size_t)(l0 - 2) * (2 * DI)] : 0.0f;
    float x2 = (l0 - 1 >= 0) ? xi[(size_t)(l0 - 1) * (2 * DI)] : 0.0f;

    for (int l = l0; l < l0 + 64; l++) {
        const float x3 = xi[(size_t)l * (2 * DI)];
        float v = x0 * w0 + x1 * w1 + x2 * w2 + x3 * w3 + bias;
        v = v / (1.0f + __expf(-v));                 // SiLU
        g_xs[(size_t)(b * LSEQ + l) * DI + d] = v;
        x0 = x1; x1 = x2; x2 = x3;
    }
}

// ---------------------------------------------------------------------------
// A = -exp(clip(A_log, -10, 2))
// ---------------------------------------------------------------------------
__global__ void aprep(const float* __restrict__ A_log)
{
    const int i = blockIdx.x * 256 + threadIdx.x;
    if (i < DI * DS) {
        float a = A_log[i];
        a = fminf(fmaxf(a, -10.0f), 2.0f);
        g_A[i] = -__expf(a);
    }
}

// ---------------------------------------------------------------------------
// B/C projections: g_bc[t][j] = sum_d xs[t,d] * W[d,j] + bias, j<16 -> B else C.
// One warp per token; lane = output column j. x broadcast via same-address LDG.
// grid 512, block 256 (8 tokens per block).
// ---------------------------------------------------------------------------
__global__ __launch_bounds__(256)
void bc_kernel(const float* __restrict__ Wb, const float* __restrict__ bb,
               const float* __restrict__ Wc, const float* __restrict__ bcv)
{
    const int warp = threadIdx.x >> 5;
    const int j    = threadIdx.x & 31;
    const int t    = blockIdx.x * 8 + warp;

    const float* xrow = g_xs + (size_t)t * DI;
    const float* W    = (j < 16) ? Wb : Wc;
    const int    jj   = j & 15;

    float acc = 0.0f;
    for (int d = 0; d < DI; d += 4) {
        const float4 xv = *(const float4*)(xrow + d);
        acc = fmaf(xv.x, W[(d + 0) * DS + jj], acc);
        acc = fmaf(xv.y, W[(d + 1) * DS + jj], acc);
        acc = fmaf(xv.z, W[(d + 2) * DS + jj], acc);
        acc = fmaf(xv.w, W[(d + 3) * DS + jj], acc);
    }
    acc += (j < 16) ? bb[jj] : bcv[jj];
    g_bc[(size_t)t * 32 + j] = acc;
}

// ---------------------------------------------------------------------------
// Selective scan. Block = 64 threads = 8 channels of one batch; each thread
// owns 2 states (thread = ch*8 + sg, states {2sg, 2sg+1}). y reduced over the
// 8 threads of a channel with shfl-xor (no per-step barriers). Inputs staged
// through shared in 32-step chunks, next chunk prefetched into registers so
// DRAM latency hides under the chunk's compute.
// grid (256, 2), block 64.
// ---------------------------------------------------------------------------
#define SC_CHUNK 32
__global__ __launch_bounds__(64)
void scan_kernel(const float* __restrict__ Dvec)
{
    __shared__ float4 bc_sh[SC_CHUNK][8];   // [step][sg] = {B2g, B2g+1, C2g, C2g+1}
    __shared__ float  x_sh [SC_CHUNK][8];   // [step][ch]
    __shared__ float  y_sh [SC_CHUNK][8];   // [step][ch]

    const int tid = threadIdx.x;
    const int b   = blockIdx.y;
    const int c0  = blockIdx.x * 8;
    const int ch  = tid >> 3;               // 0..7
    const int sg  = tid & 7;                // 0..7
    const int d   = c0 + ch;

    const float a0 = g_A[d * DS + 2 * sg];
    const float a1 = g_A[d * DS + 2 * sg + 1];
    const float dD = Dvec[d];
    const size_t tokBase = (size_t)b * LSEQ;

    float h0 = 0.0f, h1 = 0.0f;

    float  rx[4];
    float4 rbc[4];

    // prefetch chunk 0
#pragma unroll
    for (int i = 0; i < 4; i++) {
        const int e = i * 64 + tid;
        const int st = e >> 3, g = e & 7;
        const float2 bp = *(const float2*)(g_bc + (tokBase + st) * 32 + 2 * g);
        const float2 cp = *(const float2*)(g_bc + (tokBase + st) * 32 + 16 + 2 * g);
        rbc[i] = make_float4(bp.x, bp.y, cp.x, cp.y);
        rx[i]  = g_xs[(tokBase + st) * DI + c0 + g];
    }

    const int NC = LSEQ / SC_CHUNK;         // 64
    for (int c = 0; c < NC; c++) {
        // stage chunk into shared
#pragma unroll
        for (int i = 0; i < 4; i++) {
            const int e = i * 64 + tid;
            x_sh [e >> 3][e & 7] = rx[i];
            bc_sh[e >> 3][e & 7] = rbc[i];
        }
        __syncthreads();

        // prefetch next chunk (latency overlaps the 32 compute steps below)
        if (c + 1 < NC) {
            const size_t l1 = tokBase + (size_t)(c + 1) * SC_CHUNK;
#pragma unroll
            for (int i = 0; i < 4; i++) {
                const int e = i * 64 + tid;
                const int st = e >> 3, g = e & 7;
                const float2 bp = *(const float2*)(g_bc + (l1 + st) * 32 + 2 * g);
                const float2 cp = *(const float2*)(g_bc + (l1 + st) * 32 + 16 + 2 * g);
                rbc[i] = make_float4(bp.x, bp.y, cp.x, cp.y);
                rx[i]  = g_xs[(l1 + st) * DI + c0 + g];
            }
        }

#pragma unroll 8
        for (int s = 0; s < SC_CHUNK; s++) {
            const float4 bc = bc_sh[s][sg];
            const float  xv = x_sh[s][ch];
            h0 = fminf(fmaxf(fmaf(h0, a0, xv * bc.x), -100.0f), 100.0f);
            h1 = fminf(fmaxf(fmaf(h1, a1, xv * bc.y), -100.0f), 100.0f);
            float yp = h0 * bc.z + h1 * bc.w;
            yp += __shfl_xor_sync(0xffffffffu, yp, 1);
            yp += __shfl_xor_sync(0xffffffffu, yp, 2);
            yp += __shfl_xor_sync(0xffffffffu, yp, 4);
            if (sg == 0) {
                const float yo = fmaf(dD, xv, yp);
                y_sh[s][ch] = fminf(fmaxf(yo, -100.0f), 100.0f);
            }
        }
        __syncthreads();

        // coalesced writeback of this chunk's y
        const size_t lc = tokBase + (size_t)c * SC_CHUNK;
#pragma unroll
        for (int i = 0; i < 4; i++) {
            const int e = i * 64 + tid;
            const int st = e >> 3, g = e & 7;
            g_ys[(lc + st) * DI + c0 + g] = y_sh[st][g];
        }
    }
}

// ---------------------------------------------------------------------------
extern "C" void kernel_launch(void* const* d_in, const int* in_sizes, int n_in,
                              void* d_out, int out_size)
{
    const float* x      = (const float*)d_in[0];
    const float* W_in   = (const float*)d_in[1];
    const float* b_in   = (const float*)d_in[2];
    const float* W_conv = (const float*)d_in[3];
    const float* b_conv = (const float*)d_in[4];
    const float* A_log  = (const float*)d_in[5];
    const float* Dv     = (const float*)d_in[6];
    const float* W_B    = (const float*)d_in[7];
    const float* b_B    = (const float*)d_in[8];
    const float* W_C    = (const float*)d_in[9];
    const float* b_C    = (const float*)d_in[10];
    const float* W_out  = (const float*)d_in[11];
    const float* b_out  = (const float*)d_in[12];
    float* out = (float*)d_out;

    // 1. xz = x @ W_in + b_in   -> g_xz
    gemm_k<TOK, 2 * DI, DM, false><<<dim3((2 * DI) / 128, TOK / 128), 256>>>(
        x, W_in, b_in, nullptr);

    // 2. depthwise causal conv + SiLU -> g_xs
    conv_silu<<<dim3(DI / 128, LSEQ / 64, NB), 128>>>(W_conv, b_conv);

    // 3. A = -exp(clip(A_log))
    aprep<<<(DI * DS + 255) / 256, 256>>>(A_log);

    // 4. B/C projections -> g_bc
    bc_kernel<<<TOK / 8, 256>>>(W_B, b_B, W_C, b_C);

    // 5. selective scan -> g_ys
    scan_kernel<<<dim3(DI / 8, NB), 64>>>(Dv);

    // 6. out = (ys * sigmoid(z)) @ W_out + b_out
    gemm_k<TOK, DM, DI, true><<<dim3(DM / 128, TOK / 128), 256>>>(
        nullptr, W_out, b_out, out);
}

// round 6
// speedup vs baseline: 2.4172x; 2.4172x over previous
#include <cuda_runtime.h>
#include <cuda_bf16.h>
#include <cstdint>

// ---------------------------------------------------------------------------
// SSMBlock on GB300 — Round 3: warp-level HMMA (mma.sync bf16) split GEMMs.
// tcgen05 is unavailable (harness compiles PTX for plain sm_103, no 'a').
//   B=2, L=2048, D_MODEL=1024, D_INNER=2048, D_STATE=16, D_CONV=4
// ---------------------------------------------------------------------------

#define TOK   4096
#define DM    1024
#define DI    2048
#define DS    16
#define LSEQ  2048
#define NB    2

__device__ float g_xz[(size_t)TOK * 2 * DI];
__device__ float g_xs[(size_t)TOK * DI];
__device__ float g_bc[(size_t)TOK * 32];
__device__ float g_ys[(size_t)TOK * DI];
__device__ float g_A [DI * DS];

__device__ __nv_bfloat16 g_xhi[(size_t)TOK * DM];
__device__ __nv_bfloat16 g_xlo[(size_t)TOK * DM];
__device__ __nv_bfloat16 g_w1hi[(size_t)(2 * DI) * DM];
__device__ __nv_bfloat16 g_w1lo[(size_t)(2 * DI) * DM];
__device__ __nv_bfloat16 g_a2hi[(size_t)TOK * DI];
__device__ __nv_bfloat16 g_a2lo[(size_t)TOK * DI];
__device__ __nv_bfloat16 g_w2hi[(size_t)DM * DI];
__device__ __nv_bfloat16 g_w2lo[(size_t)DM * DI];

__device__ __forceinline__ float sigmoidf_(float v) {
    return 1.0f / (1.0f + __expf(-v));
}

__device__ __forceinline__ uint32_t smem_u32(const void* p) {
    uint32_t a;
    asm("{ .reg .u64 t; cvta.to.shared.u64 t, %1; cvt.u32.u64 %0, t; }"
        : "=r"(a) : "l"(p));
    return a;
}

__device__ __forceinline__ void cp_async16(uint32_t dst, const void* src) {
    asm volatile("cp.async.cg.shared.global [%0], [%1], 16;"
                 :: "r"(dst), "l"(src) : "memory");
}
__device__ __forceinline__ void cp_commit() {
    asm volatile("cp.async.commit_group;" ::: "memory");
}
template<int N>
__device__ __forceinline__ void cp_wait() {
    asm volatile("cp.async.wait_group %0;" :: "n"(N) : "memory");
}

__device__ __forceinline__ void ldsm_x4(uint32_t* r, uint32_t addr) {
    asm volatile("ldmatrix.sync.aligned.m8n8.x4.shared.b16 {%0,%1,%2,%3}, [%4];"
                 : "=r"(r[0]), "=r"(r[1]), "=r"(r[2]), "=r"(r[3]) : "r"(addr));
}

__device__ __forceinline__ void mma_bf16(float* c, const uint32_t* a, const uint32_t* b) {
    asm volatile(
        "mma.sync.aligned.m16n8k16.row.col.f32.bf16.bf16.f32 "
        "{%0,%1,%2,%3}, {%4,%5,%6,%7}, {%8,%9}, {%0,%1,%2,%3};"
        : "+f"(c[0]), "+f"(c[1]), "+f"(c[2]), "+f"(c[3])
        : "r"(a[0]), "r"(a[1]), "r"(a[2]), "r"(a[3]), "r"(b[0]), "r"(b[1]));
}

// ============================ pre-processing ===============================
__global__ __launch_bounds__(256)
void split_arr(const float* __restrict__ in, __nv_bfloat16* __restrict__ hi,
               __nv_bfloat16* __restrict__ lo, int n4)
{
    const int i = blockIdx.x * 256 + threadIdx.x;
    if (i >= n4) return;
    const float4 v = ((const float4*)in)[i];
    __nv_bfloat16 h0 = __float2bfloat16(v.x), h1 = __float2bfloat16(v.y);
    __nv_bfloat16 h2 = __float2bfloat16(v.z), h3 = __float2bfloat16(v.w);
    __nv_bfloat162* H = (__nv_bfloat162*)(hi + (size_t)i * 4);
    __nv_bfloat162* L = (__nv_bfloat162*)(lo + (size_t)i * 4);
    H[0] = __nv_bfloat162(h0, h1);
    H[1] = __nv_bfloat162(h2, h3);
    L[0] = __nv_bfloat162(__float2bfloat16(v.x - __bfloat162float(h0)),
                          __float2bfloat16(v.y - __bfloat162float(h1)));
    L[1] = __nv_bfloat162(__float2bfloat16(v.z - __bfloat162float(h2)),
                          __float2bfloat16(v.w - __bfloat162float(h3)));
}

__global__ __launch_bounds__(256)
void transpose_split(const float* __restrict__ in, __nv_bfloat16* __restrict__ hi,
                     __nv_bfloat16* __restrict__ lo, int R, int C)
{
    __shared__ float t[32][33];
    const int c0 = blockIdx.x * 32, r0 = blockIdx.y * 32;
    const int tx = threadIdx.x & 31, ty = threadIdx.x >> 5;
#pragma unroll
    for (int i = 0; i < 32; i += 8)
        t[ty + i][tx] = in[(size_t)(r0 + ty + i) * C + c0 + tx];
    __syncthreads();
#pragma unroll
    for (int i = 0; i < 32; i += 8) {
        const float v = t[tx][ty + i];
        const __nv_bfloat16 h = __float2bfloat16(v);
        const size_t o = (size_t)(c0 + ty + i) * R + r0 + tx;
        hi[o] = h;
        lo[o] = __float2bfloat16(v - __bfloat162float(h));
    }
}

__global__ __launch_bounds__(256)
void gate_split(int n4)
{
    const int i = blockIdx.x * 256 + threadIdx.x;
    if (i >= n4) return;
    const int t = i / (DI / 4);
    const int rem = i % (DI / 4);
    const float4 y = ((const float4*)g_ys)[i];
    const float4 z = *(const float4*)(g_xz + (size_t)t * (2 * DI) + DI + rem * 4);
    float4 v;
    v.x = y.x * sigmoidf_(z.x); v.y = y.y * sigmoidf_(z.y);
    v.z = y.z * sigmoidf_(z.z); v.w = y.w * sigmoidf_(z.w);
    __nv_bfloat16 h0 = __float2bfloat16(v.x), h1 = __float2bfloat16(v.y);
    __nv_bfloat16 h2 = __float2bfloat16(v.z), h3 = __float2bfloat16(v.w);
    __nv_bfloat162* H = (__nv_bfloat162*)(g_a2hi + (size_t)i * 4);
    __nv_bfloat162* L = (__nv_bfloat162*)(g_a2lo + (size_t)i * 4);
    H[0] = __nv_bfloat162(h0, h1);
    H[1] = __nv_bfloat162(h2, h3);
    L[0] = __nv_bfloat162(__float2bfloat16(v.x - __bfloat162float(h0)),
                          __float2bfloat16(v.y - __bfloat162float(h1)));
    L[1] = __nv_bfloat162(__float2bfloat16(v.z - __bfloat162float(h2)),
                          __float2bfloat16(v.w - __bfloat162float(h3)));
}

// ============================ warp-MMA GEMM ================================
// D[M,N] = A[M,K] @ W[K,N] + bias; A/W pre-split bf16 hi/lo, W transposed to
// [N][K]. 3-pass hi*hi + hi*lo + lo*hi, fp32 accum in registers.
// CTA 128x128, KC=64, 2-stage cp.async pipeline. 8 warps (4 m x 2 n), each
// 32x64 via m16n8k16. Smem tiles SW128-swizzled -> conflict-free ldmatrix.
#define KC 64
#define TILE_B 16384                         // 128 rows * 128 bytes
#define STAGE_B (4 * TILE_B)                 // Ahi Alo Bhi Blo

template<int KTOT, int NTOT>
__global__ __launch_bounds__(256)
void gemm_mma(const __nv_bfloat16* __restrict__ Ahi, const __nv_bfloat16* __restrict__ Alo,
              const __nv_bfloat16* __restrict__ Bhi, const __nv_bfloat16* __restrict__ Blo,
              const float* __restrict__ bias, float* __restrict__ Cout)
{
    extern __shared__ char sm[];
    const uint32_t sb = smem_u32(sm);

    const int tid  = threadIdx.x;
    const int lane = tid & 31;
    const int wid  = tid >> 5;
    const int wm   = wid & 3;                // 4 warps along M (32 rows each)
    const int wn   = wid >> 2;               // 2 warps along N (64 cols each)
    const int row0 = blockIdx.y * 128;
    const int col0 = blockIdx.x * 128;

    float acc[2][8][4];
#pragma unroll
    for (int i = 0; i < 2; i++)
#pragma unroll
        for (int n = 0; n < 8; n++)
#pragma unroll
            for (int q = 0; q < 4; q++) acc[i][n][q] = 0.0f;

    // ---- loader: fill one stage (4 tiles) for k-chunk starting at k0 ----
    auto load_stage = [&](int st, int k0) {
        const uint32_t base = sb + st * STAGE_B;
#pragma unroll
        for (int p = 0; p < 4; p++) {
            const int idx = p * 256 + tid;   // 0..1023
            const int r   = idx >> 3;        // 0..127
            const int c8  = idx & 7;         // 16B chunk
            const uint32_t dst = base + r * 128 + ((c8 ^ (r & 7)) << 4);
            const size_t gA = (size_t)(row0 + r) * KTOT + k0 + c8 * 8;
            const size_t gB = (size_t)(col0 + r) * KTOT + k0 + c8 * 8;
            cp_async16(dst + 0 * TILE_B, Ahi + gA);
            cp_async16(dst + 1 * TILE_B, Alo + gA);
            cp_async16(dst + 2 * TILE_B, Bhi + gB);
            cp_async16(dst + 3 * TILE_B, Blo + gB);
        }
        cp_commit();
    };

    load_stage(0, 0);
    load_stage(1, KC);

    const int NCH = KTOT / KC;
    int st = 0;
    for (int kc = 0; kc < NCH; kc++) {
        cp_wait<1>();
        __syncthreads();

        const uint32_t sA  = sb + st * STAGE_B;
        const uint32_t sAl = sA + TILE_B;
        const uint32_t sBh = sA + 2 * TILE_B;
        const uint32_t sBl = sA + 3 * TILE_B;

#pragma unroll
        for (int s = 0; s < KC / 16; s++) {
            // A fragments (2 m-tiles, hi+lo)
            uint32_t ah[2][4], al[2][4];
#pragma unroll
            for (int i = 0; i < 2; i++) {
                const int r  = wm * 32 + i * 16 + (lane & 15);
                const int kc8 = s * 2 + (lane >> 4);
                const uint32_t off = r * 128 + ((kc8 ^ (r & 7)) << 4);
                ldsm_x4(ah[i], sA  + off);
                ldsm_x4(al[i], sAl + off);
            }
            // B fragments (8 n-tiles, hi+lo); one x4 covers 2 n-tiles
            uint32_t bh[8][2], bl[8][2];
#pragma unroll
            for (int j = 0; j < 4; j++) {
                const int r  = wn * 64 + j * 16 + ((lane >> 4) << 3) + (lane & 7);
                const int kc8 = s * 2 + ((lane >> 3) & 1);
                const uint32_t off = r * 128 + ((kc8 ^ (r & 7)) << 4);
                uint32_t t[4];
                ldsm_x4(t, sBh + off);
                bh[2 * j][0] = t[0]; bh[2 * j][1] = t[1];
                bh[2 * j + 1][0] = t[2]; bh[2 * j + 1][1] = t[3];
                ldsm_x4(t, sBl + off);
                bl[2 * j][0] = t[0]; bl[2 * j][1] = t[1];
                bl[2 * j + 1][0] = t[2]; bl[2 * j + 1][1] = t[3];
            }
#pragma unroll
            for (int i = 0; i < 2; i++)
#pragma unroll
                for (int n = 0; n < 8; n++) {
                    mma_bf16(acc[i][n], ah[i], bh[n]);
                    mma_bf16(acc[i][n], ah[i], bl[n]);
                    mma_bf16(acc[i][n], al[i], bh[n]);
                }
        }
        __syncthreads();
        if (kc + 2 < NCH) load_stage(st, (kc + 2) * KC);
        else              cp_commit();       // keep group count in step
        st ^= 1;
    }

    // ---- epilogue: bias + fp32 store ----
#pragma unroll
    for (int i = 0; i < 2; i++) {
        const int m0 = row0 + wm * 32 + i * 16 + (lane >> 2);
#pragma unroll
        for (int n = 0; n < 8; n++) {
            const int c = col0 + wn * 64 + n * 8 + (lane & 3) * 2;
            const float b0 = bias[c], b1 = bias[c + 1];
            float2 v0 = make_float2(acc[i][n][0] + b0, acc[i][n][1] + b1);
            float2 v1 = make_float2(acc[i][n][2] + b0, acc[i][n][3] + b1);
            *(float2*)(Cout + (size_t)m0 * NTOT + c) = v0;
            *(float2*)(Cout + (size_t)(m0 + 8) * NTOT + c) = v1;
        }
    }
}

// ============================ conv + silu ==================================
__global__ __launch_bounds__(128)
void conv_silu(const float* __restrict__ Wc, const float* __restrict__ bc)
{
    const int d  = blockIdx.x * 128 + threadIdx.x;
    const int b  = blockIdx.z;
    const int l0 = blockIdx.y * 64;

    const float w0 = Wc[d * 4 + 0], w1 = Wc[d * 4 + 1];
    const float w2 = Wc[d * 4 + 2], w3 = Wc[d * 4 + 3];
    const float bias = bc[d];

    const float* xi = g_xz + (size_t)(b * LSEQ) * (2 * DI) + d;
    float x0 = (l0 - 3 >= 0) ? xi[(size_t)(l0 - 3) * (2 * DI)] : 0.0f;
    float x1 = (l0 - 2 >= 0) ? xi[(size_t)(l0 - 2) * (2 * DI)] : 0.0f;
    float x2 = (l0 - 1 >= 0) ? xi[(size_t)(l0 - 1) * (2 * DI)] : 0.0f;

    for (int l = l0; l < l0 + 64; l++) {
        const float x3 = xi[(size_t)l * (2 * DI)];
        float v = x0 * w0 + x1 * w1 + x2 * w2 + x3 * w3 + bias;
        v = v / (1.0f + __expf(-v));
        g_xs[(size_t)(b * LSEQ + l) * DI + d] = v;
        x0 = x1; x1 = x2; x2 = x3;
    }
}

__global__ void aprep(const float* __restrict__ A_log)
{
    const int i = blockIdx.x * 256 + threadIdx.x;
    if (i < DI * DS) {
        float a = A_log[i];
        a = fminf(fmaxf(a, -10.0f), 2.0f);
        g_A[i] = -__expf(a);
    }
}

// ============================ B/C projections ==============================
#define BCT 16
__global__ __launch_bounds__(256)
void bc_kernel(const float* __restrict__ Wb, const float* __restrict__ bb,
               const float* __restrict__ Wc, const float* __restrict__ bcv)
{
    __shared__ float Xs[BCT][33];
    __shared__ float Ws[32][33];
    const int tid = threadIdx.x;
    const int j   = tid & 31;
    const int tg  = tid >> 5;
    const int t0  = blockIdx.x * BCT;

    float acc0 = 0.0f, acc1 = 0.0f;
    for (int k0 = 0; k0 < DI; k0 += 32) {
        __syncthreads();
#pragma unroll
        for (int p = 0; p < 4; p++) {
            const int idx = p * 256 + tid;
            const int kk = idx >> 5, jj = idx & 31;
            Ws[kk][jj] = (jj < 16) ? Wb[(k0 + kk) * DS + jj]
                                   : Wc[(k0 + kk) * DS + (jj - 16)];
        }
#pragma unroll
        for (int p = 0; p < 2; p++) {
            const int idx = p * 256 + tid;
            const int tt = idx >> 5, kk = idx & 31;
            Xs[tt][kk] = g_xs[(size_t)(t0 + tt) * DI + k0 + kk];
        }
        __syncthreads();
#pragma unroll
        for (int kk = 0; kk < 32; kk++) {
            const float w = Ws[kk][j];
            acc0 = fmaf(Xs[2 * tg + 0][kk], w, acc0);
            acc1 = fmaf(Xs[2 * tg + 1][kk], w, acc1);
        }
    }
    const float bv = (j < 16) ? bb[j] : bcv[j - 16];
    g_bc[(size_t)(t0 + 2 * tg + 0) * 32 + j] = acc0 + bv;
    g_bc[(size_t)(t0 + 2 * tg + 1) * 32 + j] = acc1 + bv;
}

// ============================ selective scan ===============================
#define SC_CHUNK 32
__global__ __launch_bounds__(64)
void scan_kernel(const float* __restrict__ Dvec)
{
    __shared__ float4 bc_sh[SC_CHUNK][8];
    __shared__ float  x_sh [SC_CHUNK][8];
    __shared__ float  y_sh [SC_CHUNK][8];

    const int tid = threadIdx.x;
    const int b   = blockIdx.y;
    const int c0  = blockIdx.x * 8;
    const int ch  = tid >> 3;
    const int sg  = tid & 7;
    const int d   = c0 + ch;

    const float a0 = g_A[d * DS + 2 * sg];
    const float a1 = g_A[d * DS + 2 * sg + 1];
    const float dD = Dvec[d];
    const size_t tokBase = (size_t)b * LSEQ;

    float h0 = 0.0f, h1 = 0.0f;
    float  rx[4];
    float4 rbc[4];

#pragma unroll
    for (int i = 0; i < 4; i++) {
        const int e = i * 64 + tid;
        const int st = e >> 3, g = e & 7;
        const float2 bp = *(const float2*)(g_bc + (tokBase + st) * 32 + 2 * g);
        const float2 cp = *(const float2*)(g_bc + (tokBase + st) * 32 + 16 + 2 * g);
        rbc[i] = make_float4(bp.x, bp.y, cp.x, cp.y);
        rx[i]  = g_xs[(tokBase + st) * DI + c0 + g];
    }

    const int NC = LSEQ / SC_CHUNK;
    for (int c = 0; c < NC; c++) {
#pragma unroll
        for (int i = 0; i < 4; i++) {
            const int e = i * 64 + tid;
            x_sh [e >> 3][e & 7] = rx[i];
            bc_sh[e >> 3][e & 7] = rbc[i];
        }
        __syncthreads();

        if (c + 1 < NC) {
            const size_t l1 = tokBase + (size_t)(c + 1) * SC_CHUNK;
#pragma unroll
            for (int i = 0; i < 4; i++) {
                const int e = i * 64 + tid;
                const int st = e >> 3, g = e & 7;
                const float2 bp = *(const float2*)(g_bc + (l1 + st) * 32 + 2 * g);
                const float2 cp = *(const float2*)(g_bc + (l1 + st) * 32 + 16 + 2 * g);
                rbc[i] = make_float4(bp.x, bp.y, cp.x, cp.y);
                rx[i]  = g_xs[(l1 + st) * DI + c0 + g];
            }
        }

#pragma unroll 8
        for (int s = 0; s < SC_CHUNK; s++) {
            const float4 bc = bc_sh[s][sg];
            const float  xv = x_sh[s][ch];
            h0 = fminf(fmaxf(fmaf(h0, a0, xv * bc.x), -100.0f), 100.0f);
            h1 = fminf(fmaxf(fmaf(h1, a1, xv * bc.y), -100.0f), 100.0f);
            float yp = h0 * bc.z + h1 * bc.w;
            yp += __shfl_xor_sync(0xffffffffu, yp, 1);
            yp += __shfl_xor_sync(0xffffffffu, yp, 2);
            yp += __shfl_xor_sync(0xffffffffu, yp, 4);
            if (sg == 0) {
                const float yo = fmaf(dD, xv, yp);
                y_sh[s][ch] = fminf(fmaxf(yo, -100.0f), 100.0f);
            }
        }
        __syncthreads();

        const size_t lc = tokBase + (size_t)c * SC_CHUNK;
#pragma unroll
        for (int i = 0; i < 4; i++) {
            const int e = i * 64 + tid;
            const int st = e >> 3, g = e & 7;
            g_ys[(lc + st) * DI + c0 + g] = y_sh[st][g];
        }
    }
}

// ============================ launch =======================================
extern "C" void kernel_launch(void* const* d_in, const int* in_sizes, int n_in,
                              void* d_out, int out_size)
{
    const float* x      = (const float*)d_in[0];
    const float* W_in   = (const float*)d_in[1];
    const float* b_in   = (const float*)d_in[2];
    const float* W_conv = (const float*)d_in[3];
    const float* b_conv = (const float*)d_in[4];
    const float* A_log  = (const float*)d_in[5];
    const float* Dv     = (const float*)d_in[6];
    const float* W_B    = (const float*)d_in[7];
    const float* b_B    = (const float*)d_in[8];
    const float* W_C    = (const float*)d_in[9];
    const float* b_C    = (const float*)d_in[10];
    const float* W_out  = (const float*)d_in[11];
    const float* b_out  = (const float*)d_in[12];
    float* out = (float*)d_out;
    (void)in_sizes; (void)n_in; (void)out_size;

    const int GSMEM = 2 * STAGE_B;                     // 128 KB
    cudaFuncSetAttribute(gemm_mma<DM, 2 * DI>,
                         cudaFuncAttributeMaxDynamicSharedMemorySize, GSMEM);
    cudaFuncSetAttribute(gemm_mma<DI, DM>,
                         cudaFuncAttributeMaxDynamicSharedMemorySize, GSMEM);

    __nv_bfloat16 *p_xhi, *p_xlo, *p_w1hi, *p_w1lo, *p_a2hi, *p_a2lo, *p_w2hi, *p_w2lo;
    float* p_xz;
    cudaGetSymbolAddress((void**)&p_xhi,  g_xhi);
    cudaGetSymbolAddress((void**)&p_xlo,  g_xlo);
    cudaGetSymbolAddress((void**)&p_w1hi, g_w1hi);
    cudaGetSymbolAddress((void**)&p_w1lo, g_w1lo);
    cudaGetSymbolAddress((void**)&p_a2hi, g_a2hi);
    cudaGetSymbolAddress((void**)&p_a2lo, g_a2lo);
    cudaGetSymbolAddress((void**)&p_w2hi, g_w2hi);
    cudaGetSymbolAddress((void**)&p_w2lo, g_w2lo);
    cudaGetSymbolAddress((void**)&p_xz,   g_xz);

    // weight transposes + splits, x split
    transpose_split<<<dim3((2 * DI) / 32, DM / 32), 256>>>(W_in,  p_w1hi, p_w1lo, DM, 2 * DI);
    transpose_split<<<dim3(DM / 32, DI / 32), 256>>>(W_out, p_w2hi, p_w2lo, DI, DM);
    split_arr<<<(TOK * DM / 4 + 255) / 256, 256>>>(x, p_xhi, p_xlo, TOK * DM / 4);

    // GEMM1: xz = x @ W_in + b_in -> g_xz
    gemm_mma<DM, 2 * DI><<<dim3((2 * DI) / 128, TOK / 128), 256, GSMEM>>>(
        p_xhi, p_xlo, p_w1hi, p_w1lo, b_in, p_xz);

    // conv + silu -> g_xs
    conv_silu<<<dim3(DI / 128, LSEQ / 64, NB), 128>>>(W_conv, b_conv);

    // A prep
    aprep<<<(DI * DS + 255) / 256, 256>>>(A_log);

    // B/C projections -> g_bc
    bc_kernel<<<TOK / BCT, 256>>>(W_B, b_B, W_C, b_C);

    // selective scan -> g_ys
    scan_kernel<<<dim3(DI / 8, NB), 64>>>(Dv);

    // gate + split -> g_a2
    gate_split<<<(TOK * DI / 4 + 255) / 256, 256>>>(TOK * DI / 4);

    // GEMM2: out = a2 @ W_out + b_out
    gemm_mma<DI, DM><<<dim3(DM / 128, TOK / 128), 256, GSMEM>>>(
        p_a2hi, p_a2lo, p_w2hi, p_w2lo, b_out, out);
}